// round 1
// baseline (speedup 1.0000x reference)
#include <cuda_runtime.h>

// SlidingWindowAttentionNoOverlap: B=4, S=8192, H=16, D=64, window=128.
// Fused QK -> softmax -> PV, one block per (b, h, chunk, half-of-128-queries).
// d_out layout assumption: [out: B*S*H*D floats][attn: B*S*H*384 floats].

constexpr int Bn = 4, Sn = 8192, Hn = 16, Dn = 64, Wn = 128, Cn = 64;
constexpr int KST = 66;    // padded smem row stride for Q/K/V tiles (floats)
constexpr int SST = 384;   // scores row stride (floats)
constexpr int NTHREADS = 512;
constexpr size_t SMEM_BYTES = (size_t)(64 * SST + 64 * KST + 128 * KST) * sizeof(float);

// ---------- packed f32x2 helpers (FFMA2 path; ptxas never auto-fuses) ----------
__device__ __forceinline__ unsigned long long ld2(const float* p) {
    return *reinterpret_cast<const unsigned long long*>(p);
}
__device__ __forceinline__ void st2(float* p, unsigned long long v) {
    *reinterpret_cast<unsigned long long*>(p) = v;
}
__device__ __forceinline__ unsigned long long packdup(float x) {
    unsigned long long r;
    asm("mov.b64 %0, {%1, %1};" : "=l"(r) : "f"(x));
    return r;
}
__device__ __forceinline__ void fma2(unsigned long long& d, unsigned long long a,
                                     unsigned long long b) {
    asm("fma.rn.f32x2 %0, %1, %2, %0;" : "+l"(d) : "l"(a), "l"(b));
}
__device__ __forceinline__ float2 up2(unsigned long long v) {
    float2 r;
    asm("mov.b64 {%0, %1}, %2;" : "=f"(r.x), "=f"(r.y) : "l"(v));
    return r;
}

__global__ void __launch_bounds__(NTHREADS, 1)
swa_fused(const float* __restrict__ gQ, const float* __restrict__ gK,
          const float* __restrict__ gV, float* __restrict__ gOut,
          float* __restrict__ gAttn)
{
    extern __shared__ float sm[];
    float* sS  = sm;                 // 64 x 384 scores/probs
    float* sQ  = sm + 64 * SST;      // 64 x 66
    float* sKV = sQ + 64 * KST;      // 128 x 66 (K, then V, then reduce scratch)

    const int qh   = blockIdx.x & 1;
    const int c    = blockIdx.x >> 1;
    const int h    = blockIdx.y;
    const int b    = blockIdx.z;
    const int s0   = c * Wn + qh * 64;
    const int tid  = threadIdx.x;
    const int lane = tid & 31;
    const int warp = tid >> 5;

    // global "token-row" index of query row 0 (units of H rows)
    const int rowBase = (b * Sn + s0) * Hn + h;

    // ---------------- load Q tile (64 rows x 64 floats, as float2) ----------------
    for (int idx = tid; idx < 64 * 32; idx += NTHREADS) {
        int r = idx >> 5, p = (idx & 31) << 1;
        st2(sQ + r * KST + p, ld2(gQ + (size_t)(rowBase + r * Hn) * Dn + p));
    }

    // ---------------- QK: scores for 3 neighbor chunks ----------------
    for (int e = 0; e < 3; e++) {
        const int kc = c - 1 + e;
        const int cb = e * Wn;
        if (kc >= 0 && kc < Cn) {            // uniform across block
            __syncthreads();                 // protect sKV from previous readers
            const int kRow0 = (b * Sn + kc * Wn) * Hn + h;
            for (int idx = tid; idx < 128 * 32; idx += NTHREADS) {
                int r = idx >> 5, p = (idx & 31) << 1;
                st2(sKV + r * KST + p, ld2(gK + (size_t)(kRow0 + r * Hn) * Dn + p));
            }
            __syncthreads();

            unsigned long long acc[4][4];
            #pragma unroll
            for (int i = 0; i < 4; i++)
                #pragma unroll
                for (int j = 0; j < 4; j++) acc[i][j] = 0ull;

            #pragma unroll 8
            for (int dp = 0; dp < 32; dp++) {
                unsigned long long q2[4], k2[4];
                #pragma unroll
                for (int i = 0; i < 4; i++)
                    q2[i] = ld2(sQ + (warp * 4 + i) * KST + 2 * dp);
                #pragma unroll
                for (int j = 0; j < 4; j++)
                    k2[j] = ld2(sKV + (lane + 32 * j) * KST + 2 * dp);
                #pragma unroll
                for (int i = 0; i < 4; i++)
                    #pragma unroll
                    for (int j = 0; j < 4; j++) fma2(acc[i][j], q2[i], k2[j]);
            }
            #pragma unroll
            for (int i = 0; i < 4; i++)
                #pragma unroll
                for (int j = 0; j < 4; j++) {
                    float2 v = up2(acc[i][j]);
                    sS[(warp * 4 + i) * SST + cb + lane + 32 * j] = v.x + v.y;
                }
        } else {
            // zero-padded neighbor: score = q . 0 = 0 (must stay in softmax!)
            for (int idx = tid; idx < 64 * 128; idx += NTHREADS)
                sS[(idx >> 7) * SST + cb + (idx & 127)] = 0.0f;
        }
    }
    __syncthreads();

    // ---------------- softmax over 384, write attn ----------------
    #pragma unroll
    for (int k = 0; k < 4; k++) {
        const int r = warp * 4 + k;
        float* row = sS + r * SST;
        float4 v[3];
        float mx = -1e30f;
        #pragma unroll
        for (int m = 0; m < 3; m++) {
            v[m] = *reinterpret_cast<const float4*>(row + lane * 4 + 128 * m);
            mx = fmaxf(mx, fmaxf(fmaxf(v[m].x, v[m].y), fmaxf(v[m].z, v[m].w)));
        }
        #pragma unroll
        for (int o = 16; o > 0; o >>= 1)
            mx = fmaxf(mx, __shfl_xor_sync(0xffffffffu, mx, o));
        float sum = 0.0f;
        #pragma unroll
        for (int m = 0; m < 3; m++) {
            v[m].x = __expf(v[m].x - mx);
            v[m].y = __expf(v[m].y - mx);
            v[m].z = __expf(v[m].z - mx);
            v[m].w = __expf(v[m].w - mx);
            sum += (v[m].x + v[m].y) + (v[m].z + v[m].w);
        }
        #pragma unroll
        for (int o = 16; o > 0; o >>= 1)
            sum += __shfl_xor_sync(0xffffffffu, sum, o);
        const float inv = __frcp_rn(sum);
        float* arow = gAttn + (size_t)(rowBase + r * Hn) * 384;
        #pragma unroll
        for (int m = 0; m < 3; m++) {
            float4 p4 = make_float4(v[m].x * inv, v[m].y * inv, v[m].z * inv, v[m].w * inv);
            *reinterpret_cast<float4*>(row + lane * 4 + 128 * m) = p4;   // probs for PV
            *reinterpret_cast<float4*>(arow + lane * 4 + 128 * m) = p4;  // attn output
        }
    }
    __syncthreads();

    // ---------------- PV: ctx = P @ V_ext ----------------
    // 16 warps: warp = (rowgroup 0..7) + 8*(y-half). Each warp: 8 rows, half of y.
    const int yh = warp >> 3;
    const int rb = (warp & 7) * 8;
    unsigned long long acc[8];
    #pragma unroll
    for (int i = 0; i < 8; i++) acc[i] = 0ull;

    for (int e = 0; e < 3; e++) {
        const int kc = c - 1 + e;
        const bool valid = (kc >= 0 && kc < Cn);   // uniform
        __syncthreads();
        if (valid) {
            const int vRow0 = (b * Sn + kc * Wn) * Hn + h;
            for (int idx = tid; idx < 128 * 32; idx += NTHREADS) {
                int r = idx >> 5, p = (idx & 31) << 1;
                st2(sKV + r * KST + p, ld2(gV + (size_t)(vRow0 + r * Hn) * Dn + p));
            }
        }
        __syncthreads();
        if (!valid) continue;                      // V == 0 contributes nothing
        const int cb = e * Wn;
        #pragma unroll 4
        for (int st = 0; st < 16; st++) {
            const int y4 = yh * 64 + st * 4;
            unsigned long long v0 = ld2(sKV + (y4 + 0) * KST + 2 * lane);
            unsigned long long v1 = ld2(sKV + (y4 + 1) * KST + 2 * lane);
            unsigned long long v2 = ld2(sKV + (y4 + 2) * KST + 2 * lane);
            unsigned long long v3 = ld2(sKV + (y4 + 3) * KST + 2 * lane);
            #pragma unroll
            for (int i = 0; i < 8; i++) {
                const float4 p4 =
                    *reinterpret_cast<const float4*>(sS + (rb + i) * SST + cb + y4);
                fma2(acc[i], packdup(p4.x), v0);
                fma2(acc[i], packdup(p4.y), v1);
                fma2(acc[i], packdup(p4.z), v2);
                fma2(acc[i], packdup(p4.w), v3);
            }
        }
    }

    // ---------------- cross-half reduce + store out ----------------
    __syncthreads();   // all sKV reads done; reuse as reduce scratch
    if (yh == 1) {
        #pragma unroll
        for (int i = 0; i < 8; i++) {
            float2 v = up2(acc[i]);
            *reinterpret_cast<float2*>(sKV + (rb + i) * KST + 2 * lane) = v;
        }
    }
    __syncthreads();
    if (yh == 0) {
        #pragma unroll
        for (int i = 0; i < 8; i++) {
            float2 part = *reinterpret_cast<const float2*>(sKV + (rb + i) * KST + 2 * lane);
            float2 mine = up2(acc[i]);
            float2 res = make_float2(mine.x + part.x, mine.y + part.y);
            *reinterpret_cast<float2*>(gOut + (size_t)(rowBase + (rb + i) * Hn) * Dn + 2 * lane) = res;
        }
    }
}

extern "C" void kernel_launch(void* const* d_in, const int* in_sizes, int n_in,
                              void* d_out, int out_size) {
    const float* Q = (const float*)d_in[0];
    const float* K = (const float*)d_in[1];
    const float* V = (const float*)d_in[2];
    float* out  = (float*)d_out;
    float* attn = out + (size_t)Bn * Sn * Hn * Dn;   // out first, then attn

    cudaFuncSetAttribute(swa_fused, cudaFuncAttributeMaxDynamicSharedMemorySize,
                         (int)SMEM_BYTES);
    dim3 grid(Cn * 2, Hn, Bn);   // x: chunk*2+half, y: head, z: batch
    swa_fused<<<grid, NTHREADS, SMEM_BYTES>>>(Q, K, V, out, attn);
}

// round 2
// speedup vs baseline: 1.1496x; 1.1496x over previous
#include <cuda_runtime.h>

// SlidingWindowAttentionNoOverlap: B=4, S=8192, H=16, D=64, window=128.
// Fused QK -> softmax -> PV, one block per (b, h, chunk, half-of-128-queries).
// d_out layout: [out: B*S*H*D floats][attn: B*S*H*384 floats].

constexpr int Bn = 4, Sn = 8192, Hn = 16, Dn = 64, Wn = 128, Cn = 64;
constexpr int KST = 66;    // padded smem row stride (floats): (KST/2) mod 16 == 1 -> conflict-free column loads
constexpr int SST = 384;   // scores row stride (floats)
constexpr int NT = 512;
// sS 64x384 + sK 384x66 (K then V) + sQ 64x66
constexpr size_t SMEM_BYTES = (size_t)(64 * SST + 384 * KST + 64 * KST) * sizeof(float);

// ---------- packed f32x2 helpers (FFMA2 path; ptxas never auto-fuses) ----------
__device__ __forceinline__ unsigned long long ld2(const float* p) {
    return *reinterpret_cast<const unsigned long long*>(p);
}
__device__ __forceinline__ void st2(float* p, unsigned long long v) {
    *reinterpret_cast<unsigned long long*>(p) = v;
}
__device__ __forceinline__ unsigned long long packdup(float x) {
    unsigned long long r;
    asm("mov.b64 %0, {%1, %1};" : "=l"(r) : "f"(x));
    return r;
}
__device__ __forceinline__ void fma2(unsigned long long& d, unsigned long long a,
                                     unsigned long long b) {
    asm("fma.rn.f32x2 %0, %1, %2, %0;" : "+l"(d) : "l"(a), "l"(b));
}
__device__ __forceinline__ float2 up2(unsigned long long v) {
    float2 r;
    asm("mov.b64 {%0, %1}, %2;" : "=f"(r.x), "=f"(r.y) : "l"(v));
    return r;
}

__global__ void __launch_bounds__(NT, 1)
swa_fused(const float* __restrict__ gQ, const float* __restrict__ gK,
          const float* __restrict__ gV, float* __restrict__ gOut,
          float* __restrict__ gAttn)
{
    extern __shared__ float sm[];
    float* sS = sm;                  // 64 x 384 scores/probs
    float* sK = sm + 64 * SST;       // 384 x 66 : K tiles, later V tiles
    float* sQ = sK + 384 * KST;      // 64 x 66  : Q tile, later out-reduce scratch

    const int qh   = blockIdx.x & 1;
    const int c    = blockIdx.x >> 1;
    const int h    = blockIdx.y;
    const int b    = blockIdx.z;
    const int s0   = c * Wn + qh * 64;
    const int tid  = threadIdx.x;
    const int lane = tid & 31;
    const int warp = tid >> 5;

    const int rowBase = (b * Sn + s0) * Hn + h;   // token-row index of query row 0
    const bool eok[3] = { c > 0, true, c < Cn - 1 };

    // ---------------- load Q tile (64 x 64 as float2) ----------------
    #pragma unroll
    for (int t = 0; t < 4; t++) {
        int idx = tid + t * NT, r = idx >> 5, p = (idx & 31) << 1;
        st2(sQ + r * KST + p, ld2(gQ + (size_t)(rowBase + r * Hn) * Dn + p));
    }
    // ---------------- load all valid K chunks (up to 384 x 64) ----------------
    #pragma unroll
    for (int e = 0; e < 3; e++) {
        if (eok[e]) {
            const int kRow0 = (b * Sn + (c - 1 + e) * Wn) * Hn + h;
            #pragma unroll
            for (int t = 0; t < 8; t++) {
                int idx = tid + t * NT, r = idx >> 5, p = (idx & 31) << 1;
                st2(sK + (e * 128 + r) * KST + p,
                    ld2(gK + (size_t)(kRow0 + r * Hn) * Dn + p));
            }
        }
    }
    __syncthreads();

    // ---------------- QK: tall tile 8 rows x (2x32) cols per warp ----------------
    const int rowg = warp >> 1;          // 0..7
    const int ch   = warp & 1;           // 0..1  (which 64-col half of the 128)
    const int r0   = rowg * 8;
    for (int e = 0; e < 3; e++) {
        if (eok[e]) {
            unsigned long long acc[8][2];
            #pragma unroll
            for (int i = 0; i < 8; i++) { acc[i][0] = 0ull; acc[i][1] = 0ull; }
            const float* kb = sK + (e * 128 + ch * 64 + lane) * KST;
            const float* qb = sQ + r0 * KST;
            #pragma unroll 8
            for (int dp = 0; dp < 32; dp++) {
                unsigned long long k0 = ld2(kb + 2 * dp);                // column load, 2cyc
                unsigned long long k1 = ld2(kb + 32 * KST + 2 * dp);
                #pragma unroll
                for (int i = 0; i < 8; i++) {
                    unsigned long long q = ld2(qb + i * KST + 2 * dp);   // broadcast, 1cyc
                    fma2(acc[i][0], q, k0);
                    fma2(acc[i][1], q, k1);
                }
            }
            #pragma unroll
            for (int i = 0; i < 8; i++) {
                #pragma unroll
                for (int j = 0; j < 2; j++) {
                    float2 v = up2(acc[i][j]);
                    sS[(r0 + i) * SST + e * 128 + ch * 64 + lane + 32 * j] = v.x + v.y;
                }
            }
        } else {
            // zero-padded neighbor chunk: score = 0 (must stay in softmax!)
            #pragma unroll
            for (int t = 0; t < 16; t++) {
                int idx = tid + t * NT;
                sS[(idx >> 7) * SST + e * 128 + (idx & 127)] = 0.0f;
            }
        }
    }

    // ---------------- prefetch V into registers (hidden under softmax) ----------------
    float2 vr[3][8];
    #pragma unroll
    for (int e = 0; e < 3; e++) {
        if (eok[e]) {
            const int vRow0 = (b * Sn + (c - 1 + e) * Wn) * Hn + h;
            #pragma unroll
            for (int t = 0; t < 8; t++) {
                int idx = tid + t * NT, r = idx >> 5, p = (idx & 31) << 1;
                vr[e][t] = *reinterpret_cast<const float2*>(
                    gV + (size_t)(vRow0 + r * Hn) * Dn + p);
            }
        }
    }
    __syncthreads();   // scores complete; sK/sQ readers done

    // ---------------- softmax over 384, write attn (4 rows / warp) ----------------
    #pragma unroll
    for (int k = 0; k < 4; k++) {
        const int r = warp * 4 + k;
        float* row = sS + r * SST;
        float4 v[3];
        float mx = -1e30f;
        #pragma unroll
        for (int m = 0; m < 3; m++) {
            v[m] = *reinterpret_cast<const float4*>(row + lane * 4 + 128 * m);
            mx = fmaxf(mx, fmaxf(fmaxf(v[m].x, v[m].y), fmaxf(v[m].z, v[m].w)));
        }
        #pragma unroll
        for (int o = 16; o > 0; o >>= 1)
            mx = fmaxf(mx, __shfl_xor_sync(0xffffffffu, mx, o));
        float sum = 0.0f;
        #pragma unroll
        for (int m = 0; m < 3; m++) {
            v[m].x = __expf(v[m].x - mx);
            v[m].y = __expf(v[m].y - mx);
            v[m].z = __expf(v[m].z - mx);
            v[m].w = __expf(v[m].w - mx);
            sum += (v[m].x + v[m].y) + (v[m].z + v[m].w);
        }
        #pragma unroll
        for (int o = 16; o > 0; o >>= 1)
            sum += __shfl_xor_sync(0xffffffffu, sum, o);
        const float inv = __frcp_rn(sum);
        float* arow = gAttn + (size_t)(rowBase + r * Hn) * 384;
        #pragma unroll
        for (int m = 0; m < 3; m++) {
            float4 p4 = make_float4(v[m].x * inv, v[m].y * inv, v[m].z * inv, v[m].w * inv);
            *reinterpret_cast<float4*>(row + lane * 4 + 128 * m) = p4;   // probs for PV
            *reinterpret_cast<float4*>(arow + lane * 4 + 128 * m) = p4;  // attn output
        }
    }

    // ---------------- commit prefetched V into sK ----------------
    #pragma unroll
    for (int e = 0; e < 3; e++) {
        if (eok[e]) {
            #pragma unroll
            for (int t = 0; t < 8; t++) {
                int idx = tid + t * NT, r = idx >> 5, p = (idx & 31) << 1;
                *reinterpret_cast<float2*>(sK + (e * 128 + r) * KST + p) = vr[e][t];
            }
        }
    }
    __syncthreads();

    // ---------------- PV: ctx = P @ V_ext ----------------
    // warp = rowgroup (0..7) + 8 * y-half. 8 rows/warp, half of each 128-y slab.
    const int yh = warp >> 3;
    const int rb = (warp & 7) * 8;
    unsigned long long acc[8];
    #pragma unroll
    for (int i = 0; i < 8; i++) acc[i] = 0ull;

    for (int e = 0; e < 3; e++) {
        if (!eok[e]) continue;            // V == 0 contributes nothing
        #pragma unroll 4
        for (int st = 0; st < 16; st++) {
            const int y4 = e * 128 + yh * 64 + st * 4;
            unsigned long long v0 = ld2(sK + (y4 + 0) * KST + 2 * lane);
            unsigned long long v1 = ld2(sK + (y4 + 1) * KST + 2 * lane);
            unsigned long long v2 = ld2(sK + (y4 + 2) * KST + 2 * lane);
            unsigned long long v3 = ld2(sK + (y4 + 3) * KST + 2 * lane);
            #pragma unroll
            for (int i = 0; i < 8; i++) {
                const float4 p4 =
                    *reinterpret_cast<const float4*>(sS + (rb + i) * SST + y4);  // broadcast
                fma2(acc[i], packdup(p4.x), v0);
                fma2(acc[i], packdup(p4.y), v1);
                fma2(acc[i], packdup(p4.z), v2);
                fma2(acc[i], packdup(p4.w), v3);
            }
        }
    }

    // ---------------- cross-half reduce (via sQ scratch) + store out ----------------
    if (yh == 1) {
        #pragma unroll
        for (int i = 0; i < 8; i++) {
            float2 v = up2(acc[i]);
            *reinterpret_cast<float2*>(sQ + (rb + i) * KST + 2 * lane) = v;
        }
    }
    __syncthreads();
    if (yh == 0) {
        #pragma unroll
        for (int i = 0; i < 8; i++) {
            float2 part = *reinterpret_cast<const float2*>(sQ + (rb + i) * KST + 2 * lane);
            float2 mine = up2(acc[i]);
            float2 res = make_float2(mine.x + part.x, mine.y + part.y);
            *reinterpret_cast<float2*>(
                gOut + (size_t)(rowBase + (rb + i) * Hn) * Dn + 2 * lane) = res;
        }
    }
}

extern "C" void kernel_launch(void* const* d_in, const int* in_sizes, int n_in,
                              void* d_out, int out_size) {
    const float* Q = (const float*)d_in[0];
    const float* K = (const float*)d_in[1];
    const float* V = (const float*)d_in[2];
    float* out  = (float*)d_out;
    float* attn = out + (size_t)Bn * Sn * Hn * Dn;   // out first, then attn

    cudaFuncSetAttribute(swa_fused, cudaFuncAttributeMaxDynamicSharedMemorySize,
                         (int)SMEM_BYTES);
    dim3 grid(Cn * 2, Hn, Bn);   // x: chunk*2+half, y: head, z: batch
    swa_fused<<<grid, NT, SMEM_BYTES>>>(Q, K, V, out, attn);
}

// round 3
// speedup vs baseline: 1.2087x; 1.0514x over previous
#include <cuda_runtime.h>

// SlidingWindowAttentionNoOverlap: B=4, S=8192, H=16, D=64, window=128.
// Fused QK -> softmax -> PV, one block per (b, h, chunk, half-of-128-queries).
// d_out layout: [out: B*S*H*D floats][attn: B*S*H*384 floats].

constexpr int Bn = 4, Sn = 8192, Hn = 16, Dn = 64, Wn = 128, Cn = 64;
constexpr int KST = 66;    // padded smem row stride (floats): (KST/2) mod 16 == 1 -> conflict-free column loads
constexpr int SST = 384;   // scores row stride (floats)
constexpr int NT = 512;
// sS 64x384 + sK 384x66 (K then V) + sQ 64x66
constexpr size_t SMEM_BYTES = (size_t)(64 * SST + 384 * KST + 64 * KST) * sizeof(float);

// ---------- packed f32x2 helpers (FFMA2 path; ptxas never auto-fuses) ----------
__device__ __forceinline__ unsigned long long ld2(const float* p) {
    return *reinterpret_cast<const unsigned long long*>(p);
}
__device__ __forceinline__ void st2(float* p, unsigned long long v) {
    *reinterpret_cast<unsigned long long*>(p) = v;
}
__device__ __forceinline__ unsigned long long packdup(float x) {
    unsigned long long r;
    asm("mov.b64 %0, {%1, %1};" : "=l"(r) : "f"(x));
    return r;
}
__device__ __forceinline__ void fma2(unsigned long long& d, unsigned long long a,
                                     unsigned long long b) {
    asm("fma.rn.f32x2 %0, %1, %2, %0;" : "+l"(d) : "l"(a), "l"(b));
}
__device__ __forceinline__ float2 up2(unsigned long long v) {
    float2 r;
    asm("mov.b64 {%0, %1}, %2;" : "=f"(r.x), "=f"(r.y) : "l"(v));
    return r;
}

__global__ void __launch_bounds__(NT, 1)
swa_fused(const float* __restrict__ gQ, const float* __restrict__ gK,
          const float* __restrict__ gV, float* __restrict__ gOut,
          float* __restrict__ gAttn)
{
    extern __shared__ float sm[];
    float* sS = sm;                  // 64 x 384 scores/probs
    float* sK = sm + 64 * SST;       // 384 x 66 : K tiles, later V tiles
    float* sQ = sK + 384 * KST;      // 64 x 66  : Q tile, later out-reduce scratch

    const int qh   = blockIdx.x & 1;
    const int c    = blockIdx.x >> 1;
    const int h    = blockIdx.y;
    const int b    = blockIdx.z;
    const int s0   = c * Wn + qh * 64;
    const int tid  = threadIdx.x;
    const int lane = tid & 31;
    const int warp = tid >> 5;

    const int rowBase = (b * Sn + s0) * Hn + h;   // token-row index of query row 0
    const bool eok[3] = { c > 0, true, c < Cn - 1 };

    // ---------------- load Q tile (64 x 64 as float2) ----------------
    #pragma unroll
    for (int t = 0; t < 4; t++) {
        int idx = tid + t * NT, r = idx >> 5, p = (idx & 31) << 1;
        st2(sQ + r * KST + p, ld2(gQ + (size_t)(rowBase + r * Hn) * Dn + p));
    }
    // ---------------- load all valid K chunks (up to 384 x 64) ----------------
    #pragma unroll
    for (int e = 0; e < 3; e++) {
        if (eok[e]) {
            const int kRow0 = (b * Sn + (c - 1 + e) * Wn) * Hn + h;
            #pragma unroll
            for (int t = 0; t < 8; t++) {
                int idx = tid + t * NT, r = idx >> 5, p = (idx & 31) << 1;
                st2(sK + (e * 128 + r) * KST + p,
                    ld2(gK + (size_t)(kRow0 + r * Hn) * Dn + p));
            }
        }
    }
    __syncthreads();

    // ---------------- QK: tall tile 8 rows x (2x32) cols per warp ----------------
    const int rowg = warp >> 1;          // 0..7
    const int ch   = warp & 1;           // 0..1  (which 64-col half of the 128)
    const int r0   = rowg * 8;
    for (int e = 0; e < 3; e++) {
        if (eok[e]) {
            unsigned long long acc[8][2];
            #pragma unroll
            for (int i = 0; i < 8; i++) { acc[i][0] = 0ull; acc[i][1] = 0ull; }
            const float* kb = sK + (e * 128 + ch * 64 + lane) * KST;
            const float* qb = sQ + r0 * KST;
            #pragma unroll 8
            for (int dp = 0; dp < 32; dp++) {
                unsigned long long k0 = ld2(kb + 2 * dp);                // column load, 2cyc
                unsigned long long k1 = ld2(kb + 32 * KST + 2 * dp);
                #pragma unroll
                for (int i = 0; i < 8; i++) {
                    unsigned long long q = ld2(qb + i * KST + 2 * dp);   // broadcast, 1cyc
                    fma2(acc[i][0], q, k0);
                    fma2(acc[i][1], q, k1);
                }
            }
            #pragma unroll
            for (int i = 0; i < 8; i++) {
                #pragma unroll
                for (int j = 0; j < 2; j++) {
                    float2 v = up2(acc[i][j]);
                    sS[(r0 + i) * SST + e * 128 + ch * 64 + lane + 32 * j] = v.x + v.y;
                }
            }
        } else {
            // zero-padded neighbor chunk: score = 0 (must stay in softmax!)
            #pragma unroll
            for (int t = 0; t < 16; t++) {
                int idx = tid + t * NT;
                sS[(idx >> 7) * SST + e * 128 + (idx & 127)] = 0.0f;
            }
        }
    }

    // ---------------- prefetch V into registers (hidden under softmax) ----------------
    float2 vr[3][8];
    #pragma unroll
    for (int e = 0; e < 3; e++) {
        if (eok[e]) {
            const int vRow0 = (b * Sn + (c - 1 + e) * Wn) * Hn + h;
            #pragma unroll
            for (int t = 0; t < 8; t++) {
                int idx = tid + t * NT, r = idx >> 5, p = (idx & 31) << 1;
                vr[e][t] = *reinterpret_cast<const float2*>(
                    gV + (size_t)(vRow0 + r * Hn) * Dn + p);
            }
        }
    }
    __syncthreads();   // scores complete; sK/sQ readers done

    // ---------------- softmax over 384, write attn (4 rows / warp) ----------------
    #pragma unroll
    for (int k = 0; k < 4; k++) {
        const int r = warp * 4 + k;
        float* row = sS + r * SST;
        float4 v[3];
        float mx = -1e30f;
        #pragma unroll
        for (int m = 0; m < 3; m++) {
            v[m] = *reinterpret_cast<const float4*>(row + lane * 4 + 128 * m);
            mx = fmaxf(mx, fmaxf(fmaxf(v[m].x, v[m].y), fmaxf(v[m].z, v[m].w)));
        }
        #pragma unroll
        for (int o = 16; o > 0; o >>= 1)
            mx = fmaxf(mx, __shfl_xor_sync(0xffffffffu, mx, o));
        float sum = 0.0f;
        #pragma unroll
        for (int m = 0; m < 3; m++) {
            v[m].x = __expf(v[m].x - mx);
            v[m].y = __expf(v[m].y - mx);
            v[m].z = __expf(v[m].z - mx);
            v[m].w = __expf(v[m].w - mx);
            sum += (v[m].x + v[m].y) + (v[m].z + v[m].w);
        }
        #pragma unroll
        for (int o = 16; o > 0; o >>= 1)
            sum += __shfl_xor_sync(0xffffffffu, sum, o);
        const float inv = __frcp_rn(sum);
        float* arow = gAttn + (size_t)(rowBase + r * Hn) * 384;
        #pragma unroll
        for (int m = 0; m < 3; m++) {
            float4 p4 = make_float4(v[m].x * inv, v[m].y * inv, v[m].z * inv, v[m].w * inv);
            *reinterpret_cast<float4*>(row + lane * 4 + 128 * m) = p4;   // probs for PV
            *reinterpret_cast<float4*>(arow + lane * 4 + 128 * m) = p4;  // attn output
        }
    }

    // ---------------- commit prefetched V into sK ----------------
    #pragma unroll
    for (int e = 0; e < 3; e++) {
        if (eok[e]) {
            #pragma unroll
            for (int t = 0; t < 8; t++) {
                int idx = tid + t * NT, r = idx >> 5, p = (idx & 31) << 1;
                *reinterpret_cast<float2*>(sK + (e * 128 + r) * KST + p) = vr[e][t];
            }
        }
    }
    __syncthreads();

    // ---------------- PV: ctx = P @ V_ext ----------------
    // warp = rowgroup (0..7) + 8 * y-half. 8 rows/warp, half of each 128-y slab.
    const int yh = warp >> 3;
    const int rb = (warp & 7) * 8;
    unsigned long long acc[8];
    #pragma unroll
    for (int i = 0; i < 8; i++) acc[i] = 0ull;

    for (int e = 0; e < 3; e++) {
        if (!eok[e]) continue;            // V == 0 contributes nothing
        #pragma unroll 4
        for (int st = 0; st < 16; st++) {
            const int y4 = e * 128 + yh * 64 + st * 4;
            unsigned long long v0 = ld2(sK + (y4 + 0) * KST + 2 * lane);
            unsigned long long v1 = ld2(sK + (y4 + 1) * KST + 2 * lane);
            unsigned long long v2 = ld2(sK + (y4 + 2) * KST + 2 * lane);
            unsigned long long v3 = ld2(sK + (y4 + 3) * KST + 2 * lane);
            #pragma unroll
            for (int i = 0; i < 8; i++) {
                const float4 p4 =
                    *reinterpret_cast<const float4*>(sS + (rb + i) * SST + y4);  // broadcast
                fma2(acc[i], packdup(p4.x), v0);
                fma2(acc[i], packdup(p4.y), v1);
                fma2(acc[i], packdup(p4.z), v2);
                fma2(acc[i], packdup(p4.w), v3);
            }
        }
    }

    // ---------------- cross-half reduce (via sQ scratch) + store out ----------------
    if (yh == 1) {
        #pragma unroll
        for (int i = 0; i < 8; i++) {
            float2 v = up2(acc[i]);
            *reinterpret_cast<float2*>(sQ + (rb + i) * KST + 2 * lane) = v;
        }
    }
    __syncthreads();
    if (yh == 0) {
        #pragma unroll
        for (int i = 0; i < 8; i++) {
            float2 part = *reinterpret_cast<const float2*>(sQ + (rb + i) * KST + 2 * lane);
            float2 mine = up2(acc[i]);
            float2 res = make_float2(mine.x + part.x, mine.y + part.y);
            *reinterpret_cast<float2*>(
                gOut + (size_t)(rowBase + (rb + i) * Hn) * Dn + 2 * lane) = res;
        }
    }
}

extern "C" void kernel_launch(void* const* d_in, const int* in_sizes, int n_in,
                              void* d_out, int out_size) {
    const float* Q = (const float*)d_in[0];
    const float* K = (const float*)d_in[1];
    const float* V = (const float*)d_in[2];
    float* out  = (float*)d_out;
    float* attn = out + (size_t)Bn * Sn * Hn * Dn;   // out first, then attn

    cudaFuncSetAttribute(swa_fused, cudaFuncAttributeMaxDynamicSharedMemorySize,
                         (int)SMEM_BYTES);
    dim3 grid(Cn * 2, Hn, Bn);   // x: chunk*2+half, y: head, z: batch
    swa_fused<<<grid, NT, SMEM_BYTES>>>(Q, K, V, out, attn);
}

// round 4
// speedup vs baseline: 1.2101x; 1.0012x over previous
#include <cuda_runtime.h>

// SlidingWindowAttentionNoOverlap: B=4, S=8192, H=16, D=64, window=128.
// Fused QK -> softmax -> PV, one block per (b, h, chunk, half-of-128-queries).
// d_out layout: [out: B*S*H*D floats][attn: B*S*H*384 floats].

constexpr int Bn = 4, Sn = 8192, Hn = 16, Dn = 64, Wn = 128, Cn = 64;
constexpr int KST = 66;    // padded smem row stride (floats): (KST/2) mod 16 == 1 -> conflict-free column loads
constexpr int SST = 384;   // scores row stride (floats)
constexpr int NT = 512;
// sS 64x384 + sK 384x66 (K then V) + sQ 64x66
constexpr size_t SMEM_BYTES = (size_t)(64 * SST + 384 * KST + 64 * KST) * sizeof(float);

// ---------- packed f32x2 helpers (FFMA2 path; ptxas never auto-fuses) ----------
__device__ __forceinline__ unsigned long long ld2(const float* p) {
    return *reinterpret_cast<const unsigned long long*>(p);
}
__device__ __forceinline__ void st2(float* p, unsigned long long v) {
    *reinterpret_cast<unsigned long long*>(p) = v;
}
__device__ __forceinline__ unsigned long long packdup(float x) {
    unsigned long long r;
    asm("mov.b64 %0, {%1, %1};" : "=l"(r) : "f"(x));
    return r;
}
__device__ __forceinline__ void fma2(unsigned long long& d, unsigned long long a,
                                     unsigned long long b) {
    asm("fma.rn.f32x2 %0, %1, %2, %0;" : "+l"(d) : "l"(a), "l"(b));
}
__device__ __forceinline__ float2 up2(unsigned long long v) {
    float2 r;
    asm("mov.b64 {%0, %1}, %2;" : "=f"(r.x), "=f"(r.y) : "l"(v));
    return r;
}

__global__ void __launch_bounds__(NT, 1)
swa_fused(const float* __restrict__ gQ, const float* __restrict__ gK,
          const float* __restrict__ gV, float* __restrict__ gOut,
          float* __restrict__ gAttn)
{
    extern __shared__ float sm[];
    float* sS = sm;                  // 64 x 384 scores/probs
    float* sK = sm + 64 * SST;       // 384 x 66 : K tiles, later V tiles
    float* sQ = sK + 384 * KST;      // 64 x 66  : Q tile, later out-reduce scratch

    const int qh   = blockIdx.x & 1;
    const int c    = blockIdx.x >> 1;
    const int h    = blockIdx.y;
    const int b    = blockIdx.z;
    const int s0   = c * Wn + qh * 64;
    const int tid  = threadIdx.x;
    const int lane = tid & 31;
    const int warp = tid >> 5;

    const int rowBase = (b * Sn + s0) * Hn + h;   // token-row index of query row 0
    const bool eok[3] = { c > 0, true, c < Cn - 1 };

    // ---------------- load Q tile (64 x 64 as float2) ----------------
    #pragma unroll
    for (int t = 0; t < 4; t++) {
        int idx = tid + t * NT, r = idx >> 5, p = (idx & 31) << 1;
        st2(sQ + r * KST + p, ld2(gQ + (size_t)(rowBase + r * Hn) * Dn + p));
    }
    // ---------------- load all valid K chunks (up to 384 x 64) ----------------
    #pragma unroll
    for (int e = 0; e < 3; e++) {
        if (eok[e]) {
            const int kRow0 = (b * Sn + (c - 1 + e) * Wn) * Hn + h;
            #pragma unroll
            for (int t = 0; t < 8; t++) {
                int idx = tid + t * NT, r = idx >> 5, p = (idx & 31) << 1;
                st2(sK + (e * 128 + r) * KST + p,
                    ld2(gK + (size_t)(kRow0 + r * Hn) * Dn + p));
            }
        }
    }
    __syncthreads();

    // ---------------- QK: tall tile 8 rows x (2x32) cols per warp ----------------
    const int rowg = warp >> 1;          // 0..7
    const int ch   = warp & 1;           // 0..1  (which 64-col half of the 128)
    const int r0   = rowg * 8;
    for (int e = 0; e < 3; e++) {
        if (eok[e]) {
            unsigned long long acc[8][2];
            #pragma unroll
            for (int i = 0; i < 8; i++) { acc[i][0] = 0ull; acc[i][1] = 0ull; }
            const float* kb = sK + (e * 128 + ch * 64 + lane) * KST;
            const float* qb = sQ + r0 * KST;
            #pragma unroll 8
            for (int dp = 0; dp < 32; dp++) {
                unsigned long long k0 = ld2(kb + 2 * dp);                // column load, 2cyc
                unsigned long long k1 = ld2(kb + 32 * KST + 2 * dp);
                #pragma unroll
                for (int i = 0; i < 8; i++) {
                    unsigned long long q = ld2(qb + i * KST + 2 * dp);   // broadcast, 1cyc
                    fma2(acc[i][0], q, k0);
                    fma2(acc[i][1], q, k1);
                }
            }
            #pragma unroll
            for (int i = 0; i < 8; i++) {
                #pragma unroll
                for (int j = 0; j < 2; j++) {
                    float2 v = up2(acc[i][j]);
                    sS[(r0 + i) * SST + e * 128 + ch * 64 + lane + 32 * j] = v.x + v.y;
                }
            }
        } else {
            // zero-padded neighbor chunk: score = 0 (must stay in softmax!)
            #pragma unroll
            for (int t = 0; t < 16; t++) {
                int idx = tid + t * NT;
                sS[(idx >> 7) * SST + e * 128 + (idx & 127)] = 0.0f;
            }
        }
    }

    // ---------------- prefetch V into registers (hidden under softmax) ----------------
    float2 vr[3][8];
    #pragma unroll
    for (int e = 0; e < 3; e++) {
        if (eok[e]) {
            const int vRow0 = (b * Sn + (c - 1 + e) * Wn) * Hn + h;
            #pragma unroll
            for (int t = 0; t < 8; t++) {
                int idx = tid + t * NT, r = idx >> 5, p = (idx & 31) << 1;
                vr[e][t] = *reinterpret_cast<const float2*>(
                    gV + (size_t)(vRow0 + r * Hn) * Dn + p);
            }
        }
    }
    __syncthreads();   // scores complete; sK/sQ readers done

    // ---------------- softmax over 384, write attn (4 rows / warp) ----------------
    #pragma unroll
    for (int k = 0; k < 4; k++) {
        const int r = warp * 4 + k;
        float* row = sS + r * SST;
        float4 v[3];
        float mx = -1e30f;
        #pragma unroll
        for (int m = 0; m < 3; m++) {
            v[m] = *reinterpret_cast<const float4*>(row + lane * 4 + 128 * m);
            mx = fmaxf(mx, fmaxf(fmaxf(v[m].x, v[m].y), fmaxf(v[m].z, v[m].w)));
        }
        #pragma unroll
        for (int o = 16; o > 0; o >>= 1)
            mx = fmaxf(mx, __shfl_xor_sync(0xffffffffu, mx, o));
        float sum = 0.0f;
        #pragma unroll
        for (int m = 0; m < 3; m++) {
            v[m].x = __expf(v[m].x - mx);
            v[m].y = __expf(v[m].y - mx);
            v[m].z = __expf(v[m].z - mx);
            v[m].w = __expf(v[m].w - mx);
            sum += (v[m].x + v[m].y) + (v[m].z + v[m].w);
        }
        #pragma unroll
        for (int o = 16; o > 0; o >>= 1)
            sum += __shfl_xor_sync(0xffffffffu, sum, o);
        const float inv = __frcp_rn(sum);
        float* arow = gAttn + (size_t)(rowBase + r * Hn) * 384;
        #pragma unroll
        for (int m = 0; m < 3; m++) {
            float4 p4 = make_float4(v[m].x * inv, v[m].y * inv, v[m].z * inv, v[m].w * inv);
            *reinterpret_cast<float4*>(row + lane * 4 + 128 * m) = p4;   // probs for PV
            *reinterpret_cast<float4*>(arow + lane * 4 + 128 * m) = p4;  // attn output
        }
    }

    // ---------------- commit prefetched V into sK ----------------
    #pragma unroll
    for (int e = 0; e < 3; e++) {
        if (eok[e]) {
            #pragma unroll
            for (int t = 0; t < 8; t++) {
                int idx = tid + t * NT, r = idx >> 5, p = (idx & 31) << 1;
                *reinterpret_cast<float2*>(sK + (e * 128 + r) * KST + p) = vr[e][t];
            }
        }
    }
    __syncthreads();

    // ---------------- PV: ctx = P @ V_ext ----------------
    // warp = rowgroup (0..7) + 8 * y-half. 8 rows/warp, half of each 128-y slab.
    const int yh = warp >> 3;
    const int rb = (warp & 7) * 8;
    unsigned long long acc[8];
    #pragma unroll
    for (int i = 0; i < 8; i++) acc[i] = 0ull;

    for (int e = 0; e < 3; e++) {
        if (!eok[e]) continue;            // V == 0 contributes nothing
        #pragma unroll 4
        for (int st = 0; st < 16; st++) {
            const int y4 = e * 128 + yh * 64 + st * 4;
            unsigned long long v0 = ld2(sK + (y4 + 0) * KST + 2 * lane);
            unsigned long long v1 = ld2(sK + (y4 + 1) * KST + 2 * lane);
            unsigned long long v2 = ld2(sK + (y4 + 2) * KST + 2 * lane);
            unsigned long long v3 = ld2(sK + (y4 + 3) * KST + 2 * lane);
            #pragma unroll
            for (int i = 0; i < 8; i++) {
                const float4 p4 =
                    *reinterpret_cast<const float4*>(sS + (rb + i) * SST + y4);  // broadcast
                fma2(acc[i], packdup(p4.x), v0);
                fma2(acc[i], packdup(p4.y), v1);
                fma2(acc[i], packdup(p4.z), v2);
                fma2(acc[i], packdup(p4.w), v3);
            }
        }
    }

    // ---------------- cross-half reduce (via sQ scratch) + store out ----------------
    if (yh == 1) {
        #pragma unroll
        for (int i = 0; i < 8; i++) {
            float2 v = up2(acc[i]);
            *reinterpret_cast<float2*>(sQ + (rb + i) * KST + 2 * lane) = v;
        }
    }
    __syncthreads();
    if (yh == 0) {
        #pragma unroll
        for (int i = 0; i < 8; i++) {
            float2 part = *reinterpret_cast<const float2*>(sQ + (rb + i) * KST + 2 * lane);
            float2 mine = up2(acc[i]);
            float2 res = make_float2(mine.x + part.x, mine.y + part.y);
            *reinterpret_cast<float2*>(
                gOut + (size_t)(rowBase + (rb + i) * Hn) * Dn + 2 * lane) = res;
        }
    }
}

extern "C" void kernel_launch(void* const* d_in, const int* in_sizes, int n_in,
                              void* d_out, int out_size) {
    const float* Q = (const float*)d_in[0];
    const float* K = (const float*)d_in[1];
    const float* V = (const float*)d_in[2];
    float* out  = (float*)d_out;
    float* attn = out + (size_t)Bn * Sn * Hn * Dn;   // out first, then attn

    cudaFuncSetAttribute(swa_fused, cudaFuncAttributeMaxDynamicSharedMemorySize,
                         (int)SMEM_BYTES);
    dim3 grid(Cn * 2, Hn, Bn);   // x: chunk*2+half, y: head, z: batch
    swa_fused<<<grid, NT, SMEM_BYTES>>>(Q, K, V, out, attn);
}

// round 7
// speedup vs baseline: 1.8418x; 1.5220x over previous
#include <cuda_runtime.h>
#include <cstdint>

// SlidingWindowAttentionNoOverlap: B=4,S=8192,H=16,D=64,w=128.
// mma.sync bf16-split path (base compute_103 PTX; no tcgen05).
// CTA = (b,h,chunk,half): 64 queries. 8 warps = 4 rowgroups x 2 col-halves(192).
// d_out layout: [out: B*S*H*64 f32][attn: B*S*H*384 f32].

constexpr int Bn = 4, Sn = 8192, Hn = 16, Dn = 64, Wn = 128, Cn = 64;
constexpr int NT = 256;

constexpr int QSTR = 144;               // Q/K smem row stride (bytes), 16B-aligned, conflict-free
constexpr int VSTR = 784;               // V^T smem row stride (bytes)
constexpr int SM_Q  = 0;                // Q hi 64x144, lo at +9216   (18432 B total)
constexpr int SM_QL = 9216;
constexpr int SM_K  = 18432;            // K hi 384x144, lo at +55296 (110592 B)
constexpr int SM_KL = 55296;
constexpr int SM_VT = 129024;           // V^T hi 64x784, lo at +50176 (100352 B)
constexpr int SM_VL = 50176;
constexpr int SMEM_TOTAL = 229376;
constexpr int SCRMS = 16384;            // bytes: mx[128] f32 then sum[128] f32 (inside Q area)
constexpr int OSTR = 66;                // out-reduce scratch stride (floats)

__device__ __forceinline__ uint32_t s2u(const void* p) {
    uint32_t a;
    asm("{ .reg .u64 t; cvta.to.shared.u64 t, %1; cvt.u32.u64 %0, t; }" : "=r"(a) : "l"(p));
    return a;
}
// pack (lo=a, hi=b) to bf16x2 + residual pack
__device__ __forceinline__ void split2(float a, float b, uint32_t& hp, uint32_t& lp) {
    uint32_t h;
    asm("cvt.rn.bf16x2.f32 %0, %1, %2;" : "=r"(h) : "f"(b), "f"(a));
    float ha = __uint_as_float(h << 16);
    float hb = __uint_as_float(h & 0xffff0000u);
    uint32_t l;
    asm("cvt.rn.bf16x2.f32 %0, %1, %2;" : "=r"(l) : "f"(b - hb), "f"(a - ha));
    hp = h; lp = l;
}
__device__ __forceinline__ void ldsm4(uint32_t r[4], uint32_t a) {
    asm volatile("ldmatrix.sync.aligned.m8n8.x4.shared.b16 {%0,%1,%2,%3}, [%4];"
        : "=r"(r[0]), "=r"(r[1]), "=r"(r[2]), "=r"(r[3]) : "r"(a));
}
__device__ __forceinline__ void mma16816(float c[4], uint32_t a0, uint32_t a1, uint32_t a2,
                                         uint32_t a3, uint32_t b0, uint32_t b1) {
    asm volatile("mma.sync.aligned.m16n8k16.row.col.f32.bf16.bf16.f32 "
        "{%0,%1,%2,%3}, {%4,%5,%6,%7}, {%8,%9}, {%0,%1,%2,%3};"
        : "+f"(c[0]), "+f"(c[1]), "+f"(c[2]), "+f"(c[3])
        : "r"(a0), "r"(a1), "r"(a2), "r"(a3), "r"(b0), "r"(b1));
}

__global__ void __launch_bounds__(NT, 1)
swa_mma(const float* __restrict__ gQ, const float* __restrict__ gK,
        const float* __restrict__ gV, float* __restrict__ gOut,
        float* __restrict__ gAttn)
{
    extern __shared__ char smem[];
    const uint32_t sb = s2u(smem);

    const int qh = blockIdx.x & 1, c = blockIdx.x >> 1;
    const int h = blockIdx.y, b = blockIdx.z;
    const int tid = threadIdx.x, lane = tid & 31, warp = tid >> 5;
    const int rg = warp >> 1, g = warp & 1;
    const int s0 = c * Wn + qh * 64;
    const int rowBase = (b * Sn + s0) * Hn + h;
    const bool e0 = (c > 0), e2 = (c < Cn - 1);

    // ================= stage Q (64x64), K (3x128x64), V^T (64x384) as bf16 hi/lo ======
    #pragma unroll
    for (int t = 0; t < 4; t++) {                       // Q
        int i = tid + t * NT, r = i >> 4, dq = (i & 15) * 4;
        float4 v = *reinterpret_cast<const float4*>(gQ + (size_t)(rowBase + r * Hn) * Dn + dq);
        uint32_t h0, l0, h1, l1;
        split2(v.x, v.y, h0, l0); split2(v.z, v.w, h1, l1);
        *reinterpret_cast<uint2*>(smem + SM_Q + r * QSTR + dq * 2) = make_uint2(h0, h1);
        *reinterpret_cast<uint2*>(smem + SM_Q + SM_QL + r * QSTR + dq * 2) = make_uint2(l0, l1);
    }
    #pragma unroll
    for (int e = 0; e < 3; e++) {
        const bool ok = (e == 0) ? e0 : (e == 2) ? e2 : true;
        if (!ok) continue;
        const int kr0 = (b * Sn + (c - 1 + e) * Wn) * Hn + h;
        #pragma unroll
        for (int t = 0; t < 8; t++) {                   // K chunk e
            int i = tid + t * NT, r = i >> 4, dq = (i & 15) * 4;
            float4 v = *reinterpret_cast<const float4*>(gK + (size_t)(kr0 + r * Hn) * Dn + dq);
            uint32_t h0, l0, h1, l1;
            split2(v.x, v.y, h0, l0); split2(v.z, v.w, h1, l1);
            char* kb = smem + SM_K + (128 * e + r) * QSTR + dq * 2;
            *reinterpret_cast<uint2*>(kb) = make_uint2(h0, h1);
            *reinterpret_cast<uint2*>(kb + SM_KL) = make_uint2(l0, l1);
        }
        #pragma unroll
        for (int t = 0; t < 4; t++) {                   // V chunk e -> V^T
            int i = tid + t * NT, y2 = i & 63, d4 = i >> 6;
            int y = 2 * y2, d = 4 * d4;
            const float* vp = gV + (size_t)(kr0 + y * Hn) * Dn + d;
            float4 va = *reinterpret_cast<const float4*>(vp);
            float4 vb = *reinterpret_cast<const float4*>(vp + (size_t)Hn * Dn);
            float ax[4] = {va.x, va.y, va.z, va.w};
            float bx[4] = {vb.x, vb.y, vb.z, vb.w};
            #pragma unroll
            for (int m = 0; m < 4; m++) {
                uint32_t hp, lp;
                split2(ax[m], bx[m], hp, lp);           // (y even -> lo, y odd -> hi)
                char* vt = smem + SM_VT + (d + m) * VSTR + (128 * e + y) * 2;
                *reinterpret_cast<uint32_t*>(vt) = hp;
                *reinterpret_cast<uint32_t*>(vt + SM_VL) = lp;
            }
        }
    }
    __syncthreads();

    // ================= QK: S[16,192] per warp, 3 split terms =========================
    float s[24][4];
    #pragma unroll
    for (int j = 0; j < 24; j++)
        #pragma unroll
        for (int k = 0; k < 4; k++) s[j][k] = 0.0f;

    const uint32_t aQrow = (uint32_t)((16 * rg + (lane & 15)) * QSTR + (lane >> 4) * 16);
    const uint32_t bKrow = (uint32_t)((g * 192 + (lane & 7) + 8 * (lane >> 4)) * QSTR
                                      + ((lane >> 3) & 1) * 16);
    #pragma unroll
    for (int kk = 0; kk < 4; kk++) {
        uint32_t ah[4], al[4];
        ldsm4(ah, sb + SM_Q + aQrow + kk * 32);
        ldsm4(al, sb + SM_Q + SM_QL + aQrow + kk * 32);
        #pragma unroll
        for (int jt = 0; jt < 24; jt += 2) {
            const bool ok = g ? (jt < 8 || e2) : (jt >= 16 || e0);
            if (ok) {
                const uint32_t ka = sb + SM_K + bKrow + jt * (8 * QSTR) + kk * 32;
                uint32_t bh[4], bl[4];
                ldsm4(bh, ka);
                mma16816(s[jt],     ah[0], ah[1], ah[2], ah[3], bh[0], bh[1]);
                mma16816(s[jt + 1], ah[0], ah[1], ah[2], ah[3], bh[2], bh[3]);
                mma16816(s[jt],     al[0], al[1], al[2], al[3], bh[0], bh[1]);
                mma16816(s[jt + 1], al[0], al[1], al[2], al[3], bh[2], bh[3]);
                ldsm4(bl, ka + SM_KL);
                mma16816(s[jt],     ah[0], ah[1], ah[2], ah[3], bl[0], bl[1]);
                mma16816(s[jt + 1], ah[0], ah[1], ah[2], ah[3], bl[2], bl[3]);
            }
        }
    }
    __syncthreads();    // all ldmatrix done; Q area reusable as scratch

    // ================= softmax over 384 (rows split 2x192 across warp pairs) ==========
    float* scr = reinterpret_cast<float*>(smem + SCRMS);   // mx[128], sum[128]
    const int lr0 = 16 * rg + (lane >> 2);                 // local row (c0/c1); +8 for c2/c3

    float mx0 = -1e30f, mx1 = -1e30f;
    #pragma unroll
    for (int j = 0; j < 24; j++) {
        mx0 = fmaxf(mx0, fmaxf(s[j][0], s[j][1]));
        mx1 = fmaxf(mx1, fmaxf(s[j][2], s[j][3]));
    }
    mx0 = fmaxf(mx0, __shfl_xor_sync(~0u, mx0, 1)); mx0 = fmaxf(mx0, __shfl_xor_sync(~0u, mx0, 2));
    mx1 = fmaxf(mx1, __shfl_xor_sync(~0u, mx1, 1)); mx1 = fmaxf(mx1, __shfl_xor_sync(~0u, mx1, 2));
    if ((lane & 3) == 0) { scr[g * 64 + lr0] = mx0; scr[g * 64 + lr0 + 8] = mx1; }
    __syncthreads();
    const float mA = fmaxf(scr[lr0], scr[64 + lr0]);
    const float mB = fmaxf(scr[lr0 + 8], scr[64 + lr0 + 8]);

    float sm0 = 0.0f, sm1 = 0.0f;
    #pragma unroll
    for (int j = 0; j < 24; j++) {
        s[j][0] = __expf(s[j][0] - mA); s[j][1] = __expf(s[j][1] - mA);
        s[j][2] = __expf(s[j][2] - mB); s[j][3] = __expf(s[j][3] - mB);
        sm0 += s[j][0] + s[j][1];
        sm1 += s[j][2] + s[j][3];
    }
    sm0 += __shfl_xor_sync(~0u, sm0, 1); sm0 += __shfl_xor_sync(~0u, sm0, 2);
    sm1 += __shfl_xor_sync(~0u, sm1, 1); sm1 += __shfl_xor_sync(~0u, sm1, 2);
    if ((lane & 3) == 0) { scr[128 + g * 64 + lr0] = sm0; scr[128 + g * 64 + lr0 + 8] = sm1; }
    __syncthreads();
    const float inv0 = __frcp_rn(scr[128 + lr0] + scr[192 + lr0]);
    const float inv1 = __frcp_rn(scr[128 + lr0 + 8] + scr[192 + lr0 + 8]);

    // ---- normalize, write attn, repack C-frags -> bf16 A-frags (hi/lo) ----
    uint32_t hi01[24], hi23[24], lo01[24], lo23[24];
    {
        float* a0p = gAttn + (size_t)(rowBase + lr0 * Hn) * 384 + g * 192 + 2 * (lane & 3);
        float* a1p = a0p + (size_t)8 * Hn * 384;
        #pragma unroll
        for (int j = 0; j < 24; j++) {
            float p0 = s[j][0] * inv0, p1 = s[j][1] * inv0;
            float p2 = s[j][2] * inv1, p3 = s[j][3] * inv1;
            *reinterpret_cast<float2*>(a0p + 8 * j) = make_float2(p0, p1);
            *reinterpret_cast<float2*>(a1p + 8 * j) = make_float2(p2, p3);
            split2(p0, p1, hi01[j], lo01[j]);
            split2(p2, p3, hi23[j], lo23[j]);
        }
    }

    // ================= PV: O[16,64] partial over this warp's 192 y ====================
    float o[8][4];
    #pragma unroll
    for (int n = 0; n < 8; n++)
        #pragma unroll
        for (int k = 0; k < 4; k++) o[n][k] = 0.0f;

    const uint32_t bVrow = (uint32_t)(((lane & 7) + 8 * (lane >> 4)) * VSTR
                                      + ((lane >> 3) & 1) * 16);
    #pragma unroll
    for (int jj = 0; jj < 12; jj++) {
        const bool ok = g ? (jj < 4 || e2) : (jj >= 8 || e0);
        if (!ok) continue;
        const uint32_t co = (uint32_t)(g * 384 + 32 * jj);     // byte offset along y
        const int t0 = 2 * jj, t1 = 2 * jj + 1;
        #pragma unroll
        for (int nt = 0; nt < 8; nt += 2) {
            const uint32_t va = sb + SM_VT + nt * (8 * VSTR) + bVrow + co;
            uint32_t bh[4], bl[4];
            ldsm4(bh, va);
            mma16816(o[nt],     hi01[t0], hi23[t0], hi01[t1], hi23[t1], bh[0], bh[1]);
            mma16816(o[nt + 1], hi01[t0], hi23[t0], hi01[t1], hi23[t1], bh[2], bh[3]);
            mma16816(o[nt],     lo01[t0], lo23[t0], lo01[t1], lo23[t1], bh[0], bh[1]);
            mma16816(o[nt + 1], lo01[t0], lo23[t0], lo01[t1], lo23[t1], bh[2], bh[3]);
            ldsm4(bl, va + SM_VL);
            mma16816(o[nt],     hi01[t0], hi23[t0], hi01[t1], hi23[t1], bl[0], bl[1]);
            mma16816(o[nt + 1], hi01[t0], hi23[t0], hi01[t1], hi23[t1], bl[2], bl[3]);
        }
    }

    // ================= cross-half reduce + store out =================================
    float* scr2 = reinterpret_cast<float*>(smem);   // 64 x OSTR floats (Q area)
    __syncthreads();
    if (g == 1) {
        #pragma unroll
        for (int nt = 0; nt < 8; nt++) {
            const int col = 8 * nt + 2 * (lane & 3);
            *reinterpret_cast<float2*>(scr2 + lr0 * OSTR + col) = make_float2(o[nt][0], o[nt][1]);
            *reinterpret_cast<float2*>(scr2 + (lr0 + 8) * OSTR + col) = make_float2(o[nt][2], o[nt][3]);
        }
    }
    __syncthreads();
    if (g == 0) {
        float* o0 = gOut + (size_t)(rowBase + lr0 * Hn) * Dn + 2 * (lane & 3);
        float* o1 = o0 + (size_t)8 * Hn * Dn;
        #pragma unroll
        for (int nt = 0; nt < 8; nt++) {
            const int col = 8 * nt + 2 * (lane & 3);
            float2 q0 = *reinterpret_cast<const float2*>(scr2 + lr0 * OSTR + col);
            float2 q1 = *reinterpret_cast<const float2*>(scr2 + (lr0 + 8) * OSTR + col);
            *reinterpret_cast<float2*>(o0 + 8 * nt) = make_float2(o[nt][0] + q0.x, o[nt][1] + q0.y);
            *reinterpret_cast<float2*>(o1 + 8 * nt) = make_float2(o[nt][2] + q1.x, o[nt][3] + q1.y);
        }
    }
}

extern "C" void kernel_launch(void* const* d_in, const int* in_sizes, int n_in,
                              void* d_out, int out_size) {
    const float* Q = (const float*)d_in[0];
    const float* K = (const float*)d_in[1];
    const float* V = (const float*)d_in[2];
    float* out  = (float*)d_out;
    float* attn = out + (size_t)Bn * Sn * Hn * Dn;

    cudaFuncSetAttribute(swa_mma, cudaFuncAttributeMaxDynamicSharedMemorySize, SMEM_TOTAL);
    dim3 grid(Cn * 2, Hn, Bn);
    swa_mma<<<grid, NT, SMEM_TOTAL>>>(Q, K, V, out, attn);
}